// round 16
// baseline (speedup 1.0000x reference)
#include <cuda_runtime.h>
#include <math.h>

#define BN 4
#define CCH 21
#define HH 96
#define WW 96
#define NN (HH*WW)          // 9216
#define NEH (HH*(WW-1))     // 9120
#define NEV ((HH-1)*WW)     // 9120
#define NE  (NEH+NEV)       // 18240
#define NTREE 8             // s = b*2 + t, t=0 low, t=1 high
#define NCHUNK 32
#define CHSZ  16            // 512 / NCHUNK
#define ROOT  (48*WW + 48)  // center root (two-pass filter is root-invariant)
#define NB2   1024          // blocker-level bins (>= max path blocker count)

// ---------------- scratch ----------------
__device__ double g_ws[NTREE*NE];
__device__ unsigned long long g_key[NTREE*NE];
__device__ double g_part[BN*NCHUNK*NE];
__device__ int    g_adj[NTREE*NN*4];
__device__ int    g_ord[NTREE*NN];     // node at BFS position
__device__ int    g_pp[NTREE*NN];      // parent BFS position
__device__ int    g_cs[NTREE*NN];      // (childcount<<14)|childstart (children contiguous)
__device__ int    g_loff[NTREE*(NN+4)];
__device__ int    g_nlev[NTREE];
__device__ float  g_w[NTREE*NN];       // weight, BFS-position indexed
__device__ int    g_blist[NTREE*NN];   // blocker positions grouped by blev
__device__ int    g_bloff[NTREE*(NB2+1)];
__device__ int    g_maxblev[NTREE];
__device__ float  g_S[BN*(CCH+1)*NN];
__device__ float  g_S2[BN*(CCH+1)*NN];
__device__ double g_acc[2];

__device__ __forceinline__ void edge_nodes(int e, int &a, int &b) {
    if (e < NEH) { int r = e / (WW-1); int c = e - r*(WW-1); a = r*WW + c; b = a + 1; }
    else         { a = e - NEH; b = a + WW; }
}

__device__ __forceinline__ unsigned long long pack_key(double w, int e) {
    unsigned long long kb = (unsigned long long)__double_as_longlong(w);
    return (kb & ~32767ull) | (unsigned long long)e;
}

__device__ __forceinline__ void two_sum(float a, float b, float &s, float &e) {
    s = __fadd_rn(a, b);
    float bp = __fsub_rn(s, a);
    e = __fadd_rn(__fsub_rn(a, __fsub_rn(s, bp)), __fsub_rn(b, bp));
}

__device__ __forceinline__ float get_val(const float* preds, const float* s1c,
                                         const float* s1n, int b, int c, int node,
                                         int srcsel) {
    if (c == CCH) return 1.0f;
    if (srcsel == 0) return 1.0f/(1.0f + expf(-preds[(b*CCH + c)*NN + node]));
    return s1c[node] / s1n[node];
}

// ---------------- kernels ----------------
__global__ void k_ew_high(const float* __restrict__ hf) {
    int idx = blockIdx.x*blockDim.x + threadIdx.x;
    if (idx >= BN*NCHUNK*NE) return;
    int b = idx / (NCHUNK*NE);
    int r = idx - b*(NCHUNK*NE);
    int ch = r / NE, e = r - ch*NE;
    int a, bb; edge_nodes(e, a, bb);
    const float* f = hf + b*512*NN + ch*CHSZ*NN;
    float sh = 0.0f, sl = 0.0f;
    #pragma unroll
    for (int c = 0; c < CHSZ; c++) {
        float av = f[c*NN+a], bv = f[c*NN+bb];
        float dh, dl; two_sum(av, -bv, dh, dl);
        float p  = __fmul_rn(dh, dh);
        float pe = __fmaf_rn(dh, dh, -p);
        pe = __fmaf_rn(__fmul_rn(2.0f, dh), dl, pe);
        float t, er; two_sum(sh, p, t, er);
        sl = __fadd_rn(sl, __fadd_rn(er, pe));
        sh = t;
    }
    g_part[(b*NCHUNK + ch)*NE + e] = (double)sh + (double)sl;
}

__global__ void k_ew_red(const float* __restrict__ lf) {
    int idx = blockIdx.x*blockDim.x + threadIdx.x;
    if (idx < 2) g_acc[idx] = 0.0;
    if (idx >= BN*NE) return;
    int b = idx / NE, e = idx - b*NE;
    int a, bb; edge_nodes(e, a, bb);
    const float* f = lf + b*3*NN;
    double accl = 0.0;
    #pragma unroll
    for (int c = 0; c < 3; c++) {
        double d = (double)f[c*NN+a] - (double)f[c*NN+bb];
        accl += d*d;
    }
    g_ws[(b*2)*NE + e] = accl;
    g_key[(b*2)*NE + e] = pack_key(accl, e);
    double acc = 0.0;
    #pragma unroll 8
    for (int ch = 0; ch < NCHUNK; ch++) acc += g_part[(b*NCHUNK + ch)*NE + e];
    g_ws[(b*2+1)*NE + e] = acc;
    g_key[(b*2+1)*NE + e] = pack_key(acc, e);
}

// Fused MST (Boruvka) + ballot-BFS (sorted children -> g_cs) + weights +
// blocker-level (blev) doubling + blocker list build. One block per tree.
__global__ void __launch_bounds__(1024) k_mstbfs() {
    extern __shared__ char smraw[];
    int s = blockIdx.x;
    int tid = threadIdx.x;
    // ---------- phase 1: Boruvka ----------
    {
        unsigned long long* minw = (unsigned long long*)smraw;   // NN
        int* parent = (int*)(minw + NN);                         // NN
        int* hook   = parent + NN;                               // NN
        int* deg    = hook + NN;                                 // NN
        __shared__ int total, flag;
        const unsigned long long* key = g_key + s*NE;
        int* adj = g_adj + s*NN*4;
        for (int i = tid; i < NN; i += 1024) { parent[i] = i; deg[i] = 0; }
        for (int i = tid; i < NN*4; i += 1024) adj[i] = -1;
        if (tid == 0) total = 0;
        __syncthreads();
        for (int round = 0; round < 24; round++) {
            for (int i = tid; i < NN; i += 1024) {
                minw[i] = 0xFFFFFFFFFFFFFFFFull; hook[i] = -1;
            }
            __syncthreads();
            for (int e = tid; e < NE; e += 1024) {
                int a, b; edge_nodes(e, a, b);
                int ra = parent[a], rb = parent[b];
                if (ra != rb) {
                    unsigned long long k = key[e];
                    if (k < minw[ra]) atomicMin(&minw[ra], k);
                    if (k < minw[rb]) atomicMin(&minw[rb], k);
                }
            }
            __syncthreads();
            for (int i = tid; i < NN; i += 1024) {
                unsigned long long mk = minw[i];
                if (parent[i] == i && mk != 0xFFFFFFFFFFFFFFFFull) {
                    int e = (int)(mk & 32767ull);
                    int a, b; edge_nodes(e, a, b);
                    int ra = parent[a], rb = parent[b];
                    int other = (ra == i) ? rb : ra;
                    bool mutual = (minw[other] == mk);
                    if (!mutual || i < other) {
                        int da = atomicAdd(&deg[a], 1); adj[a*4+da] = b;
                        int db = atomicAdd(&deg[b], 1); adj[b*4+db] = a;
                        atomicAdd(&total, 1);
                        hook[i] = other;
                    }
                }
            }
            __syncthreads();
            for (int i = tid; i < NN; i += 1024) {
                int t = hook[i];
                if (t >= 0) parent[i] = t;
            }
            __syncthreads();
            for (;;) {
                if (tid == 0) flag = 0;
                __syncthreads();
                for (int i = tid; i < NN; i += 1024) {
                    int p = parent[i], gp = parent[p];
                    if (p != gp) { parent[i] = gp; flag = 1; }
                }
                __syncthreads();
                int f = flag;
                __syncthreads();
                if (!f) break;
            }
            if (total >= NN-1) break;
        }
    }
    __syncthreads();
    // ---------- phase 2: ballot BFS (children sorted by parent) ----------
    int* adj_s = (int*)smraw;   // NN*4
    int* ord   = adj_s + NN*4;  // NN
    int* pp    = ord + NN;      // NN
    {
        const int* adj = g_adj + s*NN*4;
        int* loff = g_loff + s*(NN+4);
        for (int i = tid; i < NN*4; i += 1024) adj_s[i] = adj[i];
        if (tid == 0) { ord[0] = ROOT; pp[0] = 0; loff[0] = 0; loff[1] = 1; }
        __syncthreads();
        if (tid < 32) {
            int lane = tid;
            unsigned lt = (1u << lane) - 1u;
            int cur = 0, curEnd = 1, lvl = 0;
            for (;;) {
                int total = 0;
                for (int q0 = cur; q0 < curEnd; q0 += 32) {
                    int q = q0 + lane;
                    int nc = 0; int ch[4];
                    if (q < curEnd) {
                        int u = ord[q];
                        int pu = (q == 0) ? -1 : ord[pp[q]];
                        #pragma unroll
                        for (int j = 0; j < 4; j++) {
                            int v = adj_s[u*4 + j];
                            if (v >= 0 && v != pu) ch[nc++] = v;
                        }
                    }
                    unsigned m0 = __ballot_sync(0xffffffffu, nc > 0);
                    unsigned m1 = __ballot_sync(0xffffffffu, nc > 1);
                    unsigned m2 = __ballot_sync(0xffffffffu, nc > 2);
                    unsigned m3 = __ballot_sync(0xffffffffu, nc > 3);
                    int excl = __popc(m0 & lt) + __popc(m1 & lt) + __popc(m2 & lt) + __popc(m3 & lt);
                    int base = curEnd + total + excl;
                    if (q < curEnd) {
                        for (int i = 0; i < nc; i++) { ord[base+i] = ch[i]; pp[base+i] = q; }
                        g_cs[s*NN + q] = (nc << 14) | base;
                    }
                    total += __popc(m0) + __popc(m1) + __popc(m2) + __popc(m3);
                }
                __syncwarp();
                if (total == 0) break;
                lvl++;
                if (lane == 0) loff[lvl+1] = curEnd + total;
                cur = curEnd; curEnd += total;
            }
            if (lane == 0) g_nlev[s] = lvl + 1;
        }
        __syncthreads();
        float sig = (s & 1) ? 1.0f : 0.02f;
        for (int k = tid; k < NN; k += 1024) {
            g_ord[s*NN + k] = ord[k];
            g_pp[s*NN + k]  = pp[k];
            if (k == 0) { g_w[s*NN] = 0.0f; continue; }
            int v = ord[k];
            int u = ord[pp[k]];
            int e;
            if      (u == v-1)  { int r2 = v/WW, c2 = v%WW; e = r2*(WW-1) + (c2-1); }
            else if (u == v+1)  { int r2 = v/WW, c2 = v%WW; e = r2*(WW-1) + c2; }
            else if (u == v-WW) { e = NEH + (v-WW); }
            else                { e = NEH + v; }
            g_w[s*NN + k] = expf(-(float)g_ws[s*NE + e] / sig);
        }
    }
    __syncthreads();
    // ---------- phase 3: blev doubling + blocker lists (1024 bins) ----------
    {
        int* blk = ord;   // ord done (copied out); reuse
        for (int i = tid; i < NN; i += 1024)
            blk[i] = (((g_cs[s*NN + i] >> 14) >= 2) || i == 0) ? 1 : 0;
        __syncthreads();
        int* j0 = adj_s; int* c0 = adj_s + NN; int* j1 = adj_s + 2*NN; int* c1 = adj_s + 3*NN;
        for (int i = tid; i < NN; i += 1024) {
            j0[i] = (i == 0) ? 0 : pp[i];
            c0[i] = (i == 0) ? 0 : blk[pp[i]];
        }
        __syncthreads();
        for (int r = 0; r < 14; r++) {
            for (int i = tid; i < NN; i += 1024) {
                int a = j0[i];
                c1[i] = c0[i] + c0[a];
                j1[i] = j0[a];
            }
            __syncthreads();
            int* ti;
            ti = j0; j0 = j1; j1 = ti;
            ti = c0; c0 = c1; c1 = ti;
        }
        // after even # of swaps, final counts are in (j0,c0) = adj_s base; j1/c1 free
        int* bins  = j1;   // NB2
        int* bfill = c1;   // NB2
        for (int i = tid; i < NB2; i += 1024) { bins[i] = 0; bfill[i] = 0; }
        __syncthreads();
        for (int i = tid; i < NN; i += 1024)
            if (blk[i]) { int l = min(c0[i], NB2-1); atomicAdd(&bins[l], 1); }
        __syncthreads();
        if (tid == 0) {
            int a = 0, mx = 0;
            for (int l = 0; l < NB2; l++) {
                int cnt = bins[l];
                if (cnt > 0) mx = l;
                g_bloff[s*(NB2+1) + l] = a;
                bins[l] = a;           // overwrite counts with offsets
                a += cnt;
            }
            g_bloff[s*(NB2+1) + NB2] = a;
            g_maxblev[s] = mx;
        }
        __syncthreads();
        for (int i = tid; i < NN; i += 1024)
            if (blk[i]) {
                int l = min(c0[i], NB2-1);
                int pos = bins[l] + atomicAdd(&bfill[l], 1);
                g_blist[s*NN + pos] = i;
            }
    }
}

// Tree DP fully via doubling. UP: chain-compression doubling + blocker-level
// resolution (deepest blev first; terminator blev = blev(v)+1, strict order).
// DOWN: pointer doubling (proven R14). One block per (batch, channel).
__global__ void __launch_bounds__(256) k_filter(const float* __restrict__ preds,
                                                int t, int srcsel, int dst) {
    extern __shared__ float shf[];
    float* f0 = shf;                 // NN
    float* f1 = f0 + NN;             // NN
    int*   i2 = (int*)(f1 + NN);     // NN
    float* f3 = (float*)(i2 + NN);   // NN
    float* f4 = f3 + NN;             // NN
    int*   i5 = (int*)(f4 + NN);     // NN
    __shared__ int bloffs[NB2+1];
    __shared__ int sh_maxb;
    int b = blockIdx.x, c = blockIdx.y;
    int s = b*2 + t;
    int tid = threadIdx.x;
    int nl = g_nlev[s];
    if (tid == 0) sh_maxb = g_maxblev[s];
    const float* s1c = g_S + (b*(CCH+1) + c)*NN;
    const float* s1n = g_S + (b*(CCH+1) + CCH)*NN;
    const int* ordg = g_ord + s*NN;
    const float* wg = g_w + s*NN;
    const int* csg = g_cs + s*NN;
    const int* ppg = g_pp + s*NN;
    __syncthreads();
    int maxb = sh_maxb;
    for (int i = tid; i <= maxb + 1 && i <= NB2; i += 256)
        bloffs[i] = g_bloff[s*(NB2+1) + i];
    // init triples: M[i] = al + be*M[pt]  (M = w*A' message to parent)
    for (int i = tid; i < NN; i += 256) {
        float wi = wg[i];
        int cp = csg[i]; int cc = cp >> 14;
        if (cc >= 2 || i == 0) { f0[i] = 0.f; f1[i] = 1.f; i2[i] = i; }
        else {
            float v = get_val(preds, s1c, s1n, b, c, ordg[i], srcsel);
            if (cc == 0) { f0[i] = wi*v; f1[i] = 0.f; i2[i] = i; }
            else         { f0[i] = wi*v; f1[i] = wi;  i2[i] = cp & 16383; }
        }
    }
    __syncthreads();
    int rc = 1; while ((1 << rc) < nl) rc++; rc++;
    float *A0 = f0, *B0 = f1, *A1 = f3, *B1 = f4;
    int *P0 = i2, *P1 = i5;
    for (int r = 0; r < rc; r++) {
        for (int i = tid; i < NN; i += 256) {
            int p = P0[i];
            A1[i] = __fmaf_rn(B0[i], A0[p], A0[i]);
            B1[i] = B0[i]*B0[p];
            P1[i] = P0[p];
        }
        __syncthreads();
        float* tf; int* ti;
        tf = A0; A0 = A1; A1 = tf;
        tf = B0; B0 = B1; B1 = tf;
        ti = P0; P0 = P1; P1 = ti;
    }
    // spare buffers after doubling: A1 -> Mres, B1 -> A2
    float* Mres = A1; float* A2 = B1;
    for (int i = tid; i < NN; i += 256) Mres[i] = 0.f;
    __syncthreads();
    // blocker resolution, deepest blev first
    for (int L = maxb; L >= 0; L--) {
        int s0 = bloffs[L], e0 = bloffs[L+1];
        int cnt = e0 - s0;
        if (cnt <= 32) {
            if (tid < 32) {
                if (tid < cnt) {
                    int v = g_blist[s*NN + s0 + tid];
                    float Ap = get_val(preds, s1c, s1n, b, c, ordg[v], srcsel);
                    int cp = csg[v]; int cc = cp >> 14, c0 = cp & 16383;
                    for (int j = 0; j < cc; j++) {
                        int ch = c0 + j;
                        Ap += __fmaf_rn(B0[ch], Mres[P0[ch]], A0[ch]);
                    }
                    Mres[v] = wg[v]*Ap;
                }
                __syncwarp();
            }
        } else {
            __syncthreads();
            for (int idx = s0 + tid; idx < e0; idx += 256) {
                int v = g_blist[s*NN + idx];
                float Ap = get_val(preds, s1c, s1n, b, c, ordg[v], srcsel);
                int cp = csg[v]; int cc = cp >> 14, c0 = cp & 16383;
                for (int j = 0; j < cc; j++) {
                    int ch = c0 + j;
                    Ap += __fmaf_rn(B0[ch], Mres[P0[ch]], A0[ch]);
                }
                Mres[v] = wg[v]*Ap;
            }
            __syncthreads();
        }
    }
    __syncthreads();
    // assemble A' for all nodes into A2
    for (int i = tid; i < NN; i += 256)
        A2[i] = get_val(preds, s1c, s1n, b, c, ordg[i], srcsel);
    __syncthreads();
    for (int i = tid; i < NN; i += 256) {
        if (i != 0) {
            float M = __fmaf_rn(B0[i], Mres[P0[i]], A0[i]);
            atomicAdd(&A2[ppg[i]], M);
        }
    }
    __syncthreads();
    // DOWN: pointer doubling on S = a + p*S[anc]
    for (int i = tid; i < NN; i += 256) {
        float wi = wg[i];
        A0[i] = A2[i]*(1.0f - wi*wi);
        B0[i] = wi;
        P0[i] = ppg[i];
    }
    __syncthreads();
    for (int r = 0; r < rc; r++) {
        for (int i = tid; i < NN; i += 256) {
            int an = P0[i];
            A1[i] = __fmaf_rn(B0[i], A0[an], A0[i]);
            B1[i] = B0[i]*B0[an];
            P1[i] = P0[an];
        }
        __syncthreads();
        float* tf; int* ti;
        tf = A0; A0 = A1; A1 = tf;
        tf = B0; B0 = B1; B1 = tf;
        ti = P0; P0 = P1; P1 = ti;
    }
    float* outS = ((dst == 0) ? g_S : g_S2) + (b*(CCH+1) + c)*NN;
    for (int i = tid; i < NN; i += 256) outS[ordg[i]] = A0[i];
}

__global__ void k_loss(const float* __restrict__ preds, const float* __restrict__ roi) {
    __shared__ double sl[256], sn[256];
    int idx = blockIdx.x*blockDim.x + threadIdx.x;
    double l = 0.0, n = 0.0;
    if (idx < BN*NN) {
        int b = idx / NN, i = idx - b*NN;
        int h = i / WW, w = i - h*WW;
        float r = roi[b*(2*HH)*(2*WW) + (2*h)*(2*WW) + 2*w];
        n = (double)r;
        if (r != 0.0f) {
            float nrm = g_S2[(b*(CCH+1) + CCH)*NN + i];
            double acc = 0.0;
            for (int c = 0; c < CCH; c++) {
                float pr = 1.0f/(1.0f + expf(-preds[(b*CCH + c)*NN + i]));
                float as = g_S2[(b*(CCH+1) + c)*NN + i] / nrm;
                acc += (double)fabsf(pr - as);
            }
            l = acc * (double)r;
        }
    }
    sl[threadIdx.x] = l; sn[threadIdx.x] = n;
    __syncthreads();
    for (int o = 128; o; o >>= 1) {
        if (threadIdx.x < o) { sl[threadIdx.x] += sl[threadIdx.x+o]; sn[threadIdx.x] += sn[threadIdx.x+o]; }
        __syncthreads();
    }
    if (threadIdx.x == 0) { atomicAdd(&g_acc[0], sl[0]); atomicAdd(&g_acc[1], sn[0]); }
}

__global__ void k_fin(float* out) {
    if (threadIdx.x == 0)
        out[0] = (g_acc[1] > 0.0) ? (float)(g_acc[0]/g_acc[1]) : 0.0f;
}

// ---------------- launch ----------------
extern "C" void kernel_launch(void* const* d_in, const int* in_sizes, int n_in,
                              void* d_out, int out_size) {
    const float* preds = (const float*)d_in[0];
    const float* lf    = (const float*)d_in[1];
    const float* hf    = (const float*)d_in[2];
    const float* roi   = (const float*)d_in[3];
    float* out = (float*)d_out;

    const int smem_mstbfs = 6*NN*4 + 256;   // 221440
    const int smem_filter = 6*NN*4;         // 221184 (+4KB static bloffs)
    cudaFuncSetAttribute(k_mstbfs, cudaFuncAttributeMaxDynamicSharedMemorySize, smem_mstbfs);
    cudaFuncSetAttribute(k_filter, cudaFuncAttributeMaxDynamicSharedMemorySize, smem_filter);

    dim3 g1(BN, CCH+1);
    k_ew_high<<<(BN*NCHUNK*NE + 255)/256, 256>>>(hf);            // 0
    k_ew_red <<<(BN*NE + 255)/256, 256>>>(lf);                   // 1
    k_mstbfs <<<NTREE, 1024, smem_mstbfs>>>();                   // 2
    k_filter <<<g1, 256, smem_filter>>>(preds, 0, 0, 0);         // 3  <- profiled slot
    k_filter <<<g1, 256, smem_filter>>>(preds, 1, 1, 1);         // 4
    k_loss   <<<(BN*NN + 255)/256, 256>>>(preds, roi);           // 5
    k_fin    <<<1, 32>>>(out);                                   // 6
}

// round 17
// speedup vs baseline: 1.4899x; 1.4899x over previous
#include <cuda_runtime.h>
#include <math.h>

#define BN 4
#define CCH 21
#define HH 96
#define WW 96
#define NN (HH*WW)          // 9216
#define NEH (HH*(WW-1))     // 9120
#define NEV ((HH-1)*WW)     // 9120
#define NE  (NEH+NEV)       // 18240
#define NTREE 8             // s = b*2 + t, t=0 low, t=1 high
#define NCHUNK 32
#define CHSZ  16            // 512 / NCHUNK
#define ROOT  (48*WW + 48)  // center root (two-pass filter is root-invariant)
#define RMAX  15            // max doubling rounds (2^14 >= NN)

// ---------------- scratch ----------------
__device__ double g_ws[NTREE*NE];
__device__ unsigned long long g_key[NTREE*NE];
__device__ double g_part[BN*NCHUNK*NE];
__device__ int    g_adj[NTREE*NN*4];
__device__ int    g_ord[NTREE*NN];     // node at BFS position
__device__ int    g_pp[NTREE*NN];      // parent BFS position
__device__ int    g_loff[NTREE*(NN+4)];
__device__ int    g_nlev[NTREE];
__device__ float  g_w[NTREE*NN];       // weight, BFS-position indexed
__device__ float  g_sp[NTREE*RMAX*NN]; // doubling schedule: p_r
__device__ int    g_sa[NTREE*RMAX*NN]; // doubling schedule: anc_r
__device__ int    g_rc[NTREE];         // rounds per tree
__device__ float  g_S[BN*(CCH+1)*NN];
__device__ float  g_S2[BN*(CCH+1)*NN];
__device__ double g_acc[2];

__device__ __forceinline__ void edge_nodes(int e, int &a, int &b) {
    if (e < NEH) { int r = e / (WW-1); int c = e - r*(WW-1); a = r*WW + c; b = a + 1; }
    else         { a = e - NEH; b = a + WW; }
}

__device__ __forceinline__ unsigned long long pack_key(double w, int e) {
    unsigned long long kb = (unsigned long long)__double_as_longlong(w);
    return (kb & ~32767ull) | (unsigned long long)e;
}

__device__ __forceinline__ void two_sum(float a, float b, float &s, float &e) {
    s = __fadd_rn(a, b);
    float bp = __fsub_rn(s, a);
    e = __fadd_rn(__fsub_rn(a, __fsub_rn(s, bp)), __fsub_rn(b, bp));
}

// ---------------- kernels ----------------
__global__ void k_ew_high(const float* __restrict__ hf) {
    int idx = blockIdx.x*blockDim.x + threadIdx.x;
    if (idx >= BN*NCHUNK*NE) return;
    int b = idx / (NCHUNK*NE);
    int r = idx - b*(NCHUNK*NE);
    int ch = r / NE, e = r - ch*NE;
    int a, bb; edge_nodes(e, a, bb);
    const float* f = hf + b*512*NN + ch*CHSZ*NN;
    float sh = 0.0f, sl = 0.0f;
    #pragma unroll
    for (int c = 0; c < CHSZ; c++) {
        float av = f[c*NN+a], bv = f[c*NN+bb];
        float dh, dl; two_sum(av, -bv, dh, dl);
        float p  = __fmul_rn(dh, dh);
        float pe = __fmaf_rn(dh, dh, -p);
        pe = __fmaf_rn(__fmul_rn(2.0f, dh), dl, pe);
        float t, er; two_sum(sh, p, t, er);
        sl = __fadd_rn(sl, __fadd_rn(er, pe));
        sh = t;
    }
    g_part[(b*NCHUNK + ch)*NE + e] = (double)sh + (double)sl;
}

__global__ void k_ew_red(const float* __restrict__ lf) {
    int idx = blockIdx.x*blockDim.x + threadIdx.x;
    if (idx < 2) g_acc[idx] = 0.0;
    if (idx >= BN*NE) return;
    int b = idx / NE, e = idx - b*NE;
    int a, bb; edge_nodes(e, a, bb);
    const float* f = lf + b*3*NN;
    double accl = 0.0;
    #pragma unroll
    for (int c = 0; c < 3; c++) {
        double d = (double)f[c*NN+a] - (double)f[c*NN+bb];
        accl += d*d;
    }
    g_ws[(b*2)*NE + e] = accl;
    g_key[(b*2)*NE + e] = pack_key(accl, e);
    double acc = 0.0;
    #pragma unroll 8
    for (int ch = 0; ch < NCHUNK; ch++) acc += g_part[(b*NCHUNK + ch)*NE + e];
    g_ws[(b*2+1)*NE + e] = acc;
    g_key[(b*2+1)*NE + e] = pack_key(acc, e);
}

// Fused MST (Boruvka) + BFS + weights + doubling-schedule build. 1 block/tree.
__global__ void __launch_bounds__(1024) k_mstbfs() {
    extern __shared__ char smraw[];
    int s = blockIdx.x;
    int tid = threadIdx.x;
    // ---------- phase 1: Boruvka ----------
    {
        unsigned long long* minw = (unsigned long long*)smraw;   // NN
        int* parent = (int*)(minw + NN);                         // NN
        int* hook   = parent + NN;                               // NN
        int* deg    = hook + NN;                                 // NN
        __shared__ int total, flag;
        const unsigned long long* key = g_key + s*NE;
        int* adj = g_adj + s*NN*4;
        for (int i = tid; i < NN; i += 1024) { parent[i] = i; deg[i] = 0; }
        for (int i = tid; i < NN*4; i += 1024) adj[i] = -1;
        if (tid == 0) total = 0;
        __syncthreads();
        for (int round = 0; round < 24; round++) {
            for (int i = tid; i < NN; i += 1024) {
                minw[i] = 0xFFFFFFFFFFFFFFFFull; hook[i] = -1;
            }
            __syncthreads();
            for (int e = tid; e < NE; e += 1024) {
                int a, b; edge_nodes(e, a, b);
                int ra = parent[a], rb = parent[b];
                if (ra != rb) {
                    unsigned long long k = key[e];
                    if (k < minw[ra]) atomicMin(&minw[ra], k);
                    if (k < minw[rb]) atomicMin(&minw[rb], k);
                }
            }
            __syncthreads();
            for (int i = tid; i < NN; i += 1024) {
                unsigned long long mk = minw[i];
                if (parent[i] == i && mk != 0xFFFFFFFFFFFFFFFFull) {
                    int e = (int)(mk & 32767ull);
                    int a, b; edge_nodes(e, a, b);
                    int ra = parent[a], rb = parent[b];
                    int other = (ra == i) ? rb : ra;
                    bool mutual = (minw[other] == mk);
                    if (!mutual || i < other) {
                        int da = atomicAdd(&deg[a], 1); adj[a*4+da] = b;
                        int db = atomicAdd(&deg[b], 1); adj[b*4+db] = a;
                        atomicAdd(&total, 1);
                        hook[i] = other;
                    }
                }
            }
            __syncthreads();
            for (int i = tid; i < NN; i += 1024) {
                int t = hook[i];
                if (t >= 0) parent[i] = t;
            }
            __syncthreads();
            for (;;) {
                if (tid == 0) flag = 0;
                __syncthreads();
                for (int i = tid; i < NN; i += 1024) {
                    int p = parent[i], gp = parent[p];
                    if (p != gp) { parent[i] = gp; flag = 1; }
                }
                __syncthreads();
                int f = flag;
                __syncthreads();
                if (!f) break;
            }
            if (total >= NN-1) break;
        }
    }
    __syncthreads();
    // ---------- phase 2: single-warp BFS + weights ----------
    int* adj_s = (int*)smraw;   // NN*4
    int* ord   = adj_s + NN*4;  // NN
    int* pp    = ord + NN;      // NN
    {
        const int* adj = g_adj + s*NN*4;
        int* loff = g_loff + s*(NN+4);
        for (int i = tid; i < NN*4; i += 1024) adj_s[i] = adj[i];
        if (tid == 0) { ord[0] = ROOT; pp[0] = 0; loff[0] = 0; loff[1] = 1; }
        __syncthreads();
        if (tid < 32) {
            int lane = tid;
            unsigned lt = (1u << lane) - 1u;
            int cur = 0, curEnd = 1, lvl = 0;
            for (;;) {
                int total = 0;
                for (int q0 = cur; q0 < curEnd; q0 += 32) {
                    int q = q0 + lane;
                    int nc = 0; int ch[4];
                    if (q < curEnd) {
                        int u = ord[q];
                        int pu = (q == 0) ? -1 : ord[pp[q]];
                        #pragma unroll
                        for (int j = 0; j < 4; j++) {
                            int v = adj_s[u*4 + j];
                            if (v >= 0 && v != pu) ch[nc++] = v;
                        }
                    }
                    unsigned m0 = __ballot_sync(0xffffffffu, nc > 0);
                    unsigned m1 = __ballot_sync(0xffffffffu, nc > 1);
                    unsigned m2 = __ballot_sync(0xffffffffu, nc > 2);
                    unsigned m3 = __ballot_sync(0xffffffffu, nc > 3);
                    int excl = __popc(m0 & lt) + __popc(m1 & lt) + __popc(m2 & lt) + __popc(m3 & lt);
                    int base = curEnd + total + excl;
                    if (q < curEnd) {
                        for (int i = 0; i < nc; i++) { ord[base+i] = ch[i]; pp[base+i] = q; }
                    }
                    total += __popc(m0) + __popc(m1) + __popc(m2) + __popc(m3);
                }
                __syncwarp();
                if (total == 0) break;
                lvl++;
                if (lane == 0) loff[lvl+1] = curEnd + total;
                cur = curEnd; curEnd += total;
            }
            if (lane == 0) g_nlev[s] = lvl + 1;
        }
        __syncthreads();
        float sig = (s & 1) ? 1.0f : 0.02f;
        for (int k = tid; k < NN; k += 1024) {
            g_ord[s*NN + k] = ord[k];
            g_pp[s*NN + k]  = pp[k];
            if (k == 0) { g_w[s*NN] = 0.0f; continue; }
            int v = ord[k];
            int u = ord[pp[k]];
            int e;
            if      (u == v-1)  { int r2 = v/WW, c2 = v%WW; e = r2*(WW-1) + (c2-1); }
            else if (u == v+1)  { int r2 = v/WW, c2 = v%WW; e = r2*(WW-1) + c2; }
            else if (u == v-WW) { e = NEH + (v-WW); }
            else                { e = NEH + v; }
            g_w[s*NN + k] = expf(-(float)g_ws[s*NE + e] / sig);
        }
    }
    __syncthreads();
    // ---------- phase 3: doubling-schedule build ----------
    // state_0 = (w, pp); state_r = compose(state_{r-1}); store each round.
    {
        float* p0 = (float*)adj_s;            // NN (adjacency no longer needed)
        int*   a0 = (int*)(adj_s + NN);       // NN
        float* p1 = (float*)(adj_s + 2*NN);   // NN
        int*   a1 = (int*)(adj_s + 3*NN);     // NN
        int nl = g_nlev[s];
        int rc = 1; while ((1 << rc) < nl) rc++; rc++;
        if (rc > RMAX) rc = RMAX;
        if (tid == 0) g_rc[s] = rc;
        for (int i = tid; i < NN; i += 1024) {
            p0[i] = g_w[s*NN + i];
            a0[i] = pp[i];
            g_sp[(s*RMAX + 0)*NN + i] = p0[i];
            g_sa[(s*RMAX + 0)*NN + i] = a0[i];
        }
        __syncthreads();
        for (int r = 1; r < rc; r++) {
            for (int i = tid; i < NN; i += 1024) {
                int an = a0[i];
                float pn = p0[i]*p0[an];
                int aa = a0[an];
                p1[i] = pn; a1[i] = aa;
                g_sp[(s*RMAX + r)*NN + i] = pn;
                g_sa[(s*RMAX + r)*NN + i] = aa;
            }
            __syncthreads();
            float* tf = p0; p0 = p1; p1 = tf;
            int*   ti = a0; a0 = a1; a1 = ti;
        }
    }
}

// Tree DP fully via the doubling network and its transpose.
// UP:  A' = T_0^T ... T_{rc-1}^T (val)   — reverse rounds, copy+scatter.
// DOWN: S = T_{rc-1} ... T_0 (A'(1-w^2)) — forward rounds, gather (R14-proven).
// One block per (batch, channel); smem = 2*NN floats.
__global__ void __launch_bounds__(256) k_filter(const float* __restrict__ preds,
                                                int t, int srcsel, int dst) {
    extern __shared__ float shf[];
    float* a0 = shf;        // NN
    float* a1 = a0 + NN;    // NN
    __shared__ int sh_rc;
    int b = blockIdx.x, c = blockIdx.y;
    int s = b*2 + t;
    int tid = threadIdx.x;
    if (tid == 0) sh_rc = g_rc[s];
    const float* s1c = g_S + (b*(CCH+1) + c)*NN;
    const float* s1n = g_S + (b*(CCH+1) + CCH)*NN;
    const int* ordg = g_ord + s*NN;
    // load val in BFS-position space
    for (int i = tid; i < NN; i += 256) {
        float v;
        if (c == CCH) v = 1.0f;
        else {
            int node = ordg[i];
            if (srcsel == 0) v = 1.0f/(1.0f + expf(-preds[(b*CCH + c)*NN + node]));
            else             v = s1c[node] / s1n[node];
        }
        a0[i] = v;
    }
    __syncthreads();
    int rc = sh_rc;
    // ---- UP: transposed rounds, r = rc-1 .. 0 ----
    for (int r = rc - 1; r >= 0; r--) {
        const float* pr = g_sp + (s*RMAX + r)*NN;
        const int*   ar = g_sa + (s*RMAX + r)*NN;
        for (int i = tid; i < NN; i += 256) a1[i] = a0[i];
        __syncthreads();
        for (int i = tid; i < NN; i += 256) {
            float p = pr[i];
            if (p != 0.0f) atomicAdd(&a1[ar[i]], p*a0[i]);
        }
        __syncthreads();
        float* tmp = a0; a0 = a1; a1 = tmp;
    }
    // a0 = A'. Transform for down pass: a = A'(1 - w^2)
    for (int i = tid; i < NN; i += 256) {
        float wv = g_w[s*NN + i];
        a0[i] *= (1.0f - wv*wv);
    }
    __syncthreads();
    // ---- DOWN: forward rounds, r = 0 .. rc-1 ----
    for (int r = 0; r < rc; r++) {
        const float* pr = g_sp + (s*RMAX + r)*NN;
        const int*   ar = g_sa + (s*RMAX + r)*NN;
        for (int i = tid; i < NN; i += 256) {
            float p = pr[i];
            a1[i] = (p != 0.0f) ? __fmaf_rn(p, a0[ar[i]], a0[i]) : a0[i];
        }
        __syncthreads();
        float* tmp = a0; a0 = a1; a1 = tmp;
    }
    float* outS = ((dst == 0) ? g_S : g_S2) + (b*(CCH+1) + c)*NN;
    for (int i = tid; i < NN; i += 256) outS[ordg[i]] = a0[i];
}

__global__ void k_loss(const float* __restrict__ preds, const float* __restrict__ roi) {
    __shared__ double sl[256], sn[256];
    int idx = blockIdx.x*blockDim.x + threadIdx.x;
    double l = 0.0, n = 0.0;
    if (idx < BN*NN) {
        int b = idx / NN, i = idx - b*NN;
        int h = i / WW, w = i - h*WW;
        float r = roi[b*(2*HH)*(2*WW) + (2*h)*(2*WW) + 2*w];
        n = (double)r;
        if (r != 0.0f) {
            float nrm = g_S2[(b*(CCH+1) + CCH)*NN + i];
            double acc = 0.0;
            for (int c = 0; c < CCH; c++) {
                float pr = 1.0f/(1.0f + expf(-preds[(b*CCH + c)*NN + i]));
                float as = g_S2[(b*(CCH+1) + c)*NN + i] / nrm;
                acc += (double)fabsf(pr - as);
            }
            l = acc * (double)r;
        }
    }
    sl[threadIdx.x] = l; sn[threadIdx.x] = n;
    __syncthreads();
    for (int o = 128; o; o >>= 1) {
        if (threadIdx.x < o) { sl[threadIdx.x] += sl[threadIdx.x+o]; sn[threadIdx.x] += sn[threadIdx.x+o]; }
        __syncthreads();
    }
    if (threadIdx.x == 0) { atomicAdd(&g_acc[0], sl[0]); atomicAdd(&g_acc[1], sn[0]); }
}

__global__ void k_fin(float* out) {
    if (threadIdx.x == 0)
        out[0] = (g_acc[1] > 0.0) ? (float)(g_acc[0]/g_acc[1]) : 0.0f;
}

// ---------------- launch ----------------
extern "C" void kernel_launch(void* const* d_in, const int* in_sizes, int n_in,
                              void* d_out, int out_size) {
    const float* preds = (const float*)d_in[0];
    const float* lf    = (const float*)d_in[1];
    const float* hf    = (const float*)d_in[2];
    const float* roi   = (const float*)d_in[3];
    float* out = (float*)d_out;

    const int smem_mstbfs = 6*NN*4 + 256;   // 221440
    const int smem_filter = 2*NN*4;         // 73728
    cudaFuncSetAttribute(k_mstbfs, cudaFuncAttributeMaxDynamicSharedMemorySize, smem_mstbfs);
    cudaFuncSetAttribute(k_filter, cudaFuncAttributeMaxDynamicSharedMemorySize, smem_filter);

    dim3 g1(BN, CCH+1);
    k_ew_high<<<(BN*NCHUNK*NE + 255)/256, 256>>>(hf);            // 0
    k_ew_red <<<(BN*NE + 255)/256, 256>>>(lf);                   // 1
    k_mstbfs <<<NTREE, 1024, smem_mstbfs>>>();                   // 2
    k_filter <<<g1, 256, smem_filter>>>(preds, 0, 0, 0);         // 3  <- profiled slot
    k_filter <<<g1, 256, smem_filter>>>(preds, 1, 1, 1);         // 4
    k_loss   <<<(BN*NN + 255)/256, 256>>>(preds, roi);           // 5
    k_fin    <<<1, 32>>>(out);                                   // 6
}